// round 11
// baseline (speedup 1.0000x reference)
#include <cuda_runtime.h>
#include <cuda_bf16.h>
#include <cstdint>

#define NODE 112

// Pre-split weight planes, [N][K] row-major, concatenated:
//   W1 [256][112], W2 [256][256], W3 [128][256], W4 [64][128].
#define W1_OFF 0
#define W2_OFF 28672
#define W3_OFF 94208
#define W4_OFF 126976
#define W_TOTAL 135168
__device__ __nv_bfloat16 w_hi[W_TOTAL];
__device__ __nv_bfloat16 w_lo[W_TOTAL];

// Per-graph projected activations g' (transposed [n][112], split planes).
__device__ __nv_bfloat16 gT_hi[(size_t)4096 * 256 * NODE];
__device__ __nv_bfloat16 gT_lo[(size_t)4096 * 256 * NODE];

// SMEM layout (byte offsets):
//   xs planes [112] rows x 240 B (120 bf16)           26,880 each
//   hs planes [112] rows x 512 B (256 bf16, XOR-swz)  57,344 each
//   bst region 61,440: weight tiles 3 x 18,432 OR k112 tiles 2 x 30,720
#define XS_HI_OFF 0u
#define XS_LO_OFF 26880u
#define HS_HI_OFF 53760u
#define HS_LO_OFF 111104u
#define HS_PLANE  57344u
#define BST_OFF   168448u
#define WBUF      18432u
#define WPLANE    9216u
#define WPITCH    144      // weight tile row stride (72 bf16)
#define TBUF      30720u
#define TPLANE    15360u
#define TPITCH    240      // k112 tile row stride (120 bf16)
#define G5_OFF    229888u
#define RED_OFF   230336u
#define SMEM_BYTES 230912u

__device__ __forceinline__ void split_bf16(float v, __nv_bfloat16& hi, __nv_bfloat16& lo) {
    hi = __float2bfloat16_rn(v);
    lo = __float2bfloat16_rn(v - __bfloat162float(hi));
}
__device__ __forceinline__ uint32_t pack2(__nv_bfloat16 a, __nv_bfloat16 b) {
    return (uint32_t)__bfloat16_as_ushort(a) | ((uint32_t)__bfloat16_as_ushort(b) << 16);
}

__device__ __forceinline__ void mma_bf16(float (&c)[4],
                                         uint32_t a0, uint32_t a1, uint32_t a2, uint32_t a3,
                                         uint32_t b0, uint32_t b1) {
    asm volatile("mma.sync.aligned.m16n8k16.row.col.f32.bf16.bf16.f32 "
                 "{%0,%1,%2,%3}, {%4,%5,%6,%7}, {%8,%9}, {%0,%1,%2,%3};\n"
                 : "+f"(c[0]), "+f"(c[1]), "+f"(c[2]), "+f"(c[3])
                 : "r"(a0), "r"(a1), "r"(a2), "r"(a3), "r"(b0), "r"(b1));
}
__device__ __forceinline__ void ldmat4(uint32_t& r0, uint32_t& r1, uint32_t& r2, uint32_t& r3,
                                       uint32_t addr) {
    asm volatile("ldmatrix.sync.aligned.m8n8.x4.shared.b16 {%0,%1,%2,%3}, [%4];"
                 : "=r"(r0), "=r"(r1), "=r"(r2), "=r"(r3) : "r"(addr));
}
__device__ __forceinline__ void cp16(uint32_t dst, const void* src) {
    asm volatile("cp.async.ca.shared.global [%0], [%1], 16;" :: "r"(dst), "l"(src));
}
__device__ __forceinline__ void cp_commit() { asm volatile("cp.async.commit_group;"); }
template<int N> __device__ __forceinline__ void cp_wait() {
    asm volatile("cp.async.wait_group %0;" :: "n"(N));
}

// ---- fragment machinery -----------------------------------------------------
// A addressing: non-swizzled (xs): addr = rowBase + (2*kk + aKX).
// Swizzled (hs):                   addr = rowBase + ((2*kk + aKX) ^ aSw).
template<bool ASWZ, int PB, int PLANE>
__device__ __forceinline__ void load_frags(uint32_t aHiRow, uint32_t aLoRow,
                                           uint32_t aKX, uint32_t aSw,
                                           uint32_t bH, int kk,
                                           uint32_t (&fa)[8], uint32_t (&fb)[16]) {
    const uint32_t kb = (uint32_t)(kk << 1);
    uint32_t aOff = kb + aKX;
    if (ASWZ) aOff ^= aSw;
    const uint32_t bL = bH + PLANE;
    ldmat4(fb[0],  fb[1],  fb[2],  fb[3],  bH + kb);
    ldmat4(fb[4],  fb[5],  fb[6],  fb[7],  bL + kb);
    ldmat4(fb[8],  fb[9],  fb[10], fb[11], bH + 16 * PB + kb);
    ldmat4(fb[12], fb[13], fb[14], fb[15], bL + 16 * PB + kb);
    ldmat4(fa[0], fa[1], fa[2], fa[3], aHiRow + aOff);
    ldmat4(fa[4], fa[5], fa[6], fa[7], aLoRow + aOff);
}

__device__ __forceinline__ void mma_step(float (&c)[4][4],
                                         const uint32_t (&fa)[8], const uint32_t (&fb)[16]) {
    #pragma unroll
    for (int jp = 0; jp < 2; jp++) {
        const int o = jp * 8;
        mma_bf16(c[2 * jp],     fa[0], fa[1], fa[2], fa[3], fb[o + 0], fb[o + 1]);
        mma_bf16(c[2 * jp],     fa[0], fa[1], fa[2], fa[3], fb[o + 4], fb[o + 5]);
        mma_bf16(c[2 * jp],     fa[4], fa[5], fa[6], fa[7], fb[o + 0], fb[o + 1]);
        mma_bf16(c[2 * jp + 1], fa[0], fa[1], fa[2], fa[3], fb[o + 2], fb[o + 3]);
        mma_bf16(c[2 * jp + 1], fa[0], fa[1], fa[2], fa[3], fb[o + 6], fb[o + 7]);
        mma_bf16(c[2 * jp + 1], fa[4], fa[5], fa[6], fa[7], fb[o + 2], fb[o + 3]);
    }
}

template<int Kc, int PB, int PLANE, bool ASWZ>
__device__ __forceinline__ void compute_tile(uint32_t aHiRow, uint32_t aLoRow,
                                             uint32_t aKX, uint32_t aSw,
                                             uint32_t bH, float (&c)[4][4]) {
    uint32_t fa[2][8], fb[2][16];
    load_frags<ASWZ, PB, PLANE>(aHiRow, aLoRow, aKX, aSw, bH, 0, fa[0], fb[0]);
    #pragma unroll
    for (int i = 0; i < Kc / 16; i++) {
        const int cur = i & 1;
        if ((i + 1) * 16 < Kc)
            load_frags<ASWZ, PB, PLANE>(aHiRow, aLoRow, aKX, aSw, bH,
                                        (i + 1) * 16, fa[cur ^ 1], fb[cur ^ 1]);
        mma_step(c, fa[cur], fb[cur]);
    }
}

// ---- staging ----------------------------------------------------------------
// Weight tile: [64 n][64 k] both planes, row stride 144 B.
template<int SRC_PITCH>
__device__ __forceinline__ void load_w64(uint32_t dst,
                                         const __nv_bfloat16* __restrict__ Bhi,
                                         const __nv_bfloat16* __restrict__ Blo,
                                         int n0, int k0, int tid) {
    #pragma unroll
    for (int base = 0; base < 1024; base += 512) {
        int i = base + tid;
        int p  = (i >= 512);
        int ii = p ? i - 512 : i;
        int rr = ii >> 3;
        int cc = ii & 7;
        const __nv_bfloat16* src = (p ? Blo : Bhi) + (size_t)(n0 + rr) * SRC_PITCH + k0 + cc * 8;
        cp16(dst + p * WPLANE + rr * WPITCH + cc * 16, src);
    }
}

// k112 tile: [64 n][112 k] both planes, row stride 240 B. 1792 chunks.
__device__ __forceinline__ void load_t112(uint32_t dst,
                                          const __nv_bfloat16* __restrict__ Bhi,
                                          const __nv_bfloat16* __restrict__ Blo,
                                          int n0, int tid) {
    #pragma unroll
    for (int base = 0; base < 1792; base += 512) {
        int i = base + tid;
        if (i < 1792) {
            int p  = (i >= 896);
            int ii = p ? i - 896 : i;
            int rr = ii / 14;
            int cc = ii - rr * 14;
            const __nv_bfloat16* src = (p ? Blo : Bhi) + (size_t)(n0 + rr) * NODE + cc * 8;
            cp16(dst + p * TPLANE + rr * TPITCH + cc * 16, src);
        }
    }
}

// ---- GEMM flavors -----------------------------------------------------------
// Stage-A / L1: C[112][NT] = xs[112][112] @ B^T, B from global split planes
// ([NT][112]). Single k112 tile per n-chunk, double-buffered, post-barrier
// prefetch. Output: hs = split(relu(C + bias)), XOR-swizzled, packed stores.
template<int NT>
__device__ __forceinline__ void gemm112(char* sm, uint32_t smb,
                                        const __nv_bfloat16* __restrict__ Bhi,
                                        const __nv_bfloat16* __restrict__ Blo,
                                        const float* __restrict__ bias, const int tid) {
    constexpr int NC = NT / 64;
    const int warp = tid >> 5, lane = tid & 31;
    const int g = lane >> 2, t4 = lane & 3;
    const int q = lane >> 3, r8 = lane & 7;
    const bool cw = warp < 14;
    const int rb = warp >> 1, half = warp & 1;
    const int m0 = rb * 16;

    const uint32_t aRow = (uint32_t)(m0 + r8 + ((q & 1) << 3));
    const uint32_t aKX  = (uint32_t)((q >> 1) << 4);
    const uint32_t aHiRow = smb + XS_HI_OFF + aRow * 240u;
    const uint32_t aLoRow = smb + XS_LO_OFF + aRow * 240u;
    const uint32_t bRow = (uint32_t)((half << 5) + ((q >> 1) << 3) + r8) * TPITCH
                        + (uint32_t)((q & 1) << 4);
    const uint32_t bst = smb + BST_OFF;

    __syncthreads();                       // prior epilogue writes visible
    load_t112(bst, Bhi, Blo, 0, tid);
    cp_commit();

    #pragma unroll 1
    for (int t = 0; t < NC; t++) {
        cp_wait<0>();
        __syncthreads();                   // tile t ready; old readers of other buf done
        if (t + 1 < NC) {
            load_t112(bst + (uint32_t)((t + 1) & 1) * TBUF, Bhi, Blo, (t + 1) * 64, tid);
            cp_commit();
        }
        if (cw) {
            float c[4][4];
            #pragma unroll
            for (int j = 0; j < 4; j++) { c[j][0]=0.f; c[j][1]=0.f; c[j][2]=0.f; c[j][3]=0.f; }
            const uint32_t bH = bst + (uint32_t)(t & 1) * TBUF + bRow;
            compute_tile<112, TPITCH, TPLANE, false>(aHiRow, aLoRow, aKX, 0u, bH, c);

            const int mr = m0 + g;
            const uint32_t sw = (uint32_t)((mr & 7) << 4);
            #pragma unroll
            for (int j = 0; j < 4; j++) {
                const int n = t * 64 + (half << 5) + 8 * j + 2 * t4;
                const float bv0 = __ldg(&bias[n]);
                const float bv1 = __ldg(&bias[n + 1]);
                const float v00 = fmaxf(c[j][0] + bv0, 0.f);
                const float v01 = fmaxf(c[j][1] + bv1, 0.f);
                const float v10 = fmaxf(c[j][2] + bv0, 0.f);
                const float v11 = fmaxf(c[j][3] + bv1, 0.f);
                __nv_bfloat16 h0, l0, h1, l1;
                const uint32_t a0 = HS_HI_OFF + (uint32_t)mr * 512u + (((uint32_t)(2 * n)) ^ sw);
                split_bf16(v00, h0, l0); split_bf16(v01, h1, l1);
                *(uint32_t*)(sm + a0)            = pack2(h0, h1);
                *(uint32_t*)(sm + a0 + HS_PLANE) = pack2(l0, l1);
                split_bf16(v10, h0, l0); split_bf16(v11, h1, l1);
                *(uint32_t*)(sm + a0 + 4096u)            = pack2(h0, h1);
                *(uint32_t*)(sm + a0 + 4096u + HS_PLANE) = pack2(l0, l1);
            }
        }
    }
}

// Stage-P: C[112][NT] = hs[112][KT] @ W^T. k64 tiles, triple-buffered.
// Output: gT split planes ([n][112], global).
template<int NT, int KT>
__device__ __forceinline__ void gemm_w(uint32_t smb,
                                       const __nv_bfloat16* __restrict__ Bhi,
                                       const __nv_bfloat16* __restrict__ Blo,
                                       __nv_bfloat16* __restrict__ gThi,
                                       __nv_bfloat16* __restrict__ gTlo, const int tid) {
    constexpr int NC = NT / 64;
    constexpr int KC = KT / 64;
    constexpr int T  = NC * KC;

    const int warp = tid >> 5, lane = tid & 31;
    const int g = lane >> 2, t4 = lane & 3;
    const int q = lane >> 3, r8 = lane & 7;
    const bool cw = warp < 14;
    const int rb = warp >> 1, half = warp & 1;
    const int m0 = rb * 16;

    const uint32_t aRow = (uint32_t)(m0 + r8 + ((q & 1) << 3));
    const uint32_t aColQ = (uint32_t)((q >> 1) << 4);
    const uint32_t aSw   = (uint32_t)((aRow & 7) << 4);
    const uint32_t aHiRow = smb + HS_HI_OFF + aRow * 512u;
    const uint32_t aLoRow = smb + HS_LO_OFF + aRow * 512u;
    const uint32_t bRow = (uint32_t)((half << 5) + ((q >> 1) << 3) + r8) * WPITCH
                        + (uint32_t)((q & 1) << 4);
    const uint32_t bst = smb + BST_OFF;

    __syncthreads();                       // hs writes from previous GEMM visible
    load_w64<KT>(bst, Bhi, Blo, 0, 0, tid);
    cp_commit();

    float c[4][4];
    #pragma unroll 1
    for (int t = 0; t < T; t++) {
        const int nc = t / KC, kc = t - nc * KC;
        if (t + 1 < T) {
            const int t1 = t + 1, nc1 = t1 / KC, kc1 = t1 - nc1 * KC;
            load_w64<KT>(bst + (uint32_t)((t + 1) % 3) * WBUF, Bhi, Blo, nc1 * 64, kc1 * 64, tid);
            cp_commit();
            cp_wait<1>();
        } else {
            cp_wait<0>();
        }
        __syncthreads();

        if (cw) {
            if (kc == 0) {
                #pragma unroll
                for (int j = 0; j < 4; j++) { c[j][0]=0.f; c[j][1]=0.f; c[j][2]=0.f; c[j][3]=0.f; }
            }
            const uint32_t bH = bst + (uint32_t)(t % 3) * WBUF + bRow;
            compute_tile<64, WPITCH, WPLANE, true>(aHiRow, aLoRow,
                                                   aColQ + (uint32_t)(kc << 7), aSw, bH, c);
            if (kc == KC - 1) {
                const int mr = m0 + g;
                #pragma unroll
                for (int j = 0; j < 4; j++) {
                    const int n = nc * 64 + (half << 5) + 8 * j + 2 * t4;
                    split_bf16(c[j][0], gThi[(size_t)n * NODE + mr],           gTlo[(size_t)n * NODE + mr]);
                    split_bf16(c[j][1], gThi[(size_t)(n + 1) * NODE + mr],     gTlo[(size_t)(n + 1) * NODE + mr]);
                    split_bf16(c[j][2], gThi[(size_t)n * NODE + mr + 8],       gTlo[(size_t)n * NODE + mr + 8]);
                    split_bf16(c[j][3], gThi[(size_t)(n + 1) * NODE + mr + 8], gTlo[(size_t)(n + 1) * NODE + mr + 8]);
                }
            }
        }
    }
}

__global__ void prep_weights(const float* __restrict__ W1, const float* __restrict__ W2,
                             const float* __restrict__ W3, const float* __restrict__ W4) {
    int i = blockIdx.x * 256 + threadIdx.x;
    if (i >= W_TOTAL) return;
    float v;
    if (i < W2_OFF)      v = W1[i];
    else if (i < W3_OFF) v = W2[i - W2_OFF];
    else if (i < W4_OFF) v = W3[i - W3_OFF];
    else                 v = W4[i - W4_OFF];
    split_bf16(v, w_hi[i], w_lo[i]);
}

__global__ void __launch_bounds__(512, 1)
gcn_fused_kernel(const float* __restrict__ x,
                 const float* __restrict__ b1, const float* __restrict__ b2,
                 const float* __restrict__ b3, const float* __restrict__ b4,
                 const float* __restrict__ W5, const float* __restrict__ b5,
                 const float* __restrict__ Wf, const float* __restrict__ bf,
                 float* __restrict__ out) {
    extern __shared__ char sm[];
    const uint32_t smb = (uint32_t)__cvta_generic_to_shared(sm);
    __nv_bfloat16* xs_hi = (__nv_bfloat16*)(sm + XS_HI_OFF);
    __nv_bfloat16* xs_lo = (__nv_bfloat16*)(sm + XS_LO_OFF);
    float* g5  = (float*)(sm + G5_OFF);
    float* red = (float*)(sm + RED_OFF);

    const int tid = threadIdx.x;
    const int b = blockIdx.x;
    __nv_bfloat16* gThi = gT_hi + (size_t)b * (256 * NODE);
    __nv_bfloat16* gTlo = gT_lo + (size_t)b * (256 * NODE);

    const float* xb = x + (size_t)b * (NODE * NODE);
    for (int idx = tid; idx < NODE * NODE; idx += 512) {
        int m = idx / NODE;
        int j = idx - m * NODE;
        split_bf16(xb[idx], xs_hi[m * 120 + j], xs_lo[m * 120 + j]);
    }

    // Layer 1: h = relu(x @ W1^T + b1)                      [112,256]
    gemm112<256>(sm, smb, w_hi + W1_OFF, w_lo + W1_OFF, b1, tid);
    // Layer 2: g' = h @ W2^T ; h = relu(x @ g' + b2)        [112,256]
    gemm_w<256, 256>(smb, w_hi + W2_OFF, w_lo + W2_OFF, gThi, gTlo, tid);
    gemm112<256>(sm, smb, gThi, gTlo, b2, tid);
    // Layer 3                                               [112,128]
    gemm_w<128, 256>(smb, w_hi + W3_OFF, w_lo + W3_OFF, gThi, gTlo, tid);
    gemm112<128>(sm, smb, gThi, gTlo, b3, tid);
    // Layer 4                                               [112,64]
    gemm_w<64, 128>(smb, w_hi + W4_OFF, w_lo + W4_OFF, gThi, gTlo, tid);
    gemm112<64>(sm, smb, gThi, gTlo, b4, tid);

    __syncthreads();
    // Layer 5 (project-first): g5[m] = sum_k h[m][k] * W5[k], k < 64
    if (tid < NODE) {
        const uint32_t sw = (uint32_t)((tid & 7) << 4);
        float acc = 0.f;
        #pragma unroll
        for (int k = 0; k < 64; k++) {
            const uint32_t a = HS_HI_OFF + (uint32_t)tid * 512u + (((uint32_t)(2 * k)) ^ sw);
            const float hv = __bfloat162float(*(__nv_bfloat16*)(sm + a))
                           + __bfloat162float(*(__nv_bfloat16*)(sm + a + HS_PLANE));
            acc += hv * __ldg(&W5[k]);
        }
        g5[tid] = acc;
    }
    __syncthreads();
    if (tid < NODE) {
        float acc = 0.f;
        #pragma unroll
        for (int j = 0; j < NODE; j++) {
            const float xv = __bfloat162float(xs_hi[tid * 120 + j])
                           + __bfloat162float(xs_lo[tid * 120 + j]);
            acc += xv * g5[j];
        }
        const float h5 = fmaxf(acc + __ldg(&b5[0]), 0.f);
        red[tid] = h5 * __ldg(&Wf[tid]);
    }
    __syncthreads();
    if (tid == 0) {
        float s = 0.f;
        #pragma unroll
        for (int i = 0; i < NODE; i++) s += red[i];
        out[b] = s + __ldg(&bf[0]);
    }
}

extern "C" void kernel_launch(void* const* d_in, const int* in_sizes, int n_in,
                              void* d_out, int out_size) {
    const float* x  = (const float*)d_in[0];
    const float* W1 = (const float*)d_in[1];
    const float* b1 = (const float*)d_in[2];
    const float* W2 = (const float*)d_in[3];
    const float* b2 = (const float*)d_in[4];
    const float* W3 = (const float*)d_in[5];
    const float* b3 = (const float*)d_in[6];
    const float* W4 = (const float*)d_in[7];
    const float* b4 = (const float*)d_in[8];
    const float* W5 = (const float*)d_in[9];
    const float* b5 = (const float*)d_in[10];
    const float* Wf = (const float*)d_in[11];
    const float* bf = (const float*)d_in[12];
    float* out = (float*)d_out;

    prep_weights<<<(W_TOTAL + 255) / 256, 256>>>(W1, W2, W3, W4);

    cudaFuncSetAttribute(gcn_fused_kernel,
                         cudaFuncAttributeMaxDynamicSharedMemorySize, SMEM_BYTES);
    gcn_fused_kernel<<<4096, 512, SMEM_BYTES>>>(
        x, b1, b2, b3, b4, W5, b5, Wf, bf, out);
}